// round 6
// baseline (speedup 1.0000x reference)
#include <cuda_runtime.h>
#include <cuda_fp16.h>
#include <cstdint>
#include <math.h>

// Problem shapes (fixed by setup_inputs)
#define NN 40000
#define EE 100000
#define DD 768
#define GG 128
#define D3 2304

// ---------------- scratch (static device globals; allocation-free) ----------
__device__ static __half g_xh [(size_t)NN * DD];   // x in fp16
__device__ static __half g_h0 [(size_t)NN * DD];   // h0 / t
__device__ static __half g_emb3[(size_t)NN * D3];  // concat(h1,h2,h3)
__device__ static __half g_emb[(size_t)NN * DD];   // node embedding
__device__ static __half g_yh [(size_t)GG * DD];   // y in fp16
__device__ static __half g_yp [(size_t)GG * DD];   // leaky_relu(y@py_W+py_b)
__device__ static __half g_qh [(size_t)EE * DD];   // relu(qin@pc1_W+pc1_b)
__device__ static __half g_wT [7077888];           // transposed weights [N,K] fp16

// ---------------- helpers ----------------------------------------------------
__device__ __forceinline__ uint32_t smem_u32(const void* p) {
    uint32_t a;
    asm("{ .reg .u64 t; cvta.to.shared.u64 t, %1; cvt.u32.u64 %0, t; }" : "=r"(a) : "l"(p));
    return a;
}

__device__ __forceinline__ void cp_async16(uint32_t dst, const void* src, bool pred) {
    int sz = pred ? 16 : 0;
    asm volatile("cp.async.cg.shared.global [%0], [%1], 16, %2;"
                 :: "r"(dst), "l"(src), "r"(sz) : "memory");
}
#define CP_COMMIT() asm volatile("cp.async.commit_group;" ::: "memory")
#define CP_WAIT(n)  asm volatile("cp.async.wait_group %0;" :: "n"(n) : "memory")

__device__ __forceinline__ void ldsm_x4(uint32_t& r0, uint32_t& r1, uint32_t& r2, uint32_t& r3,
                                        uint32_t addr) {
    asm volatile("ldmatrix.sync.aligned.m8n8.x4.shared.b16 {%0,%1,%2,%3}, [%4];"
                 : "=r"(r0), "=r"(r1), "=r"(r2), "=r"(r3) : "r"(addr));
}

__device__ __forceinline__ void mma_f16(float d[4], const uint32_t a[4], const uint32_t b[2]) {
    asm volatile(
        "mma.sync.aligned.m16n8k16.row.col.f32.f16.f16.f32 "
        "{%0,%1,%2,%3}, {%4,%5,%6,%7}, {%8,%9}, {%0,%1,%2,%3};"
        : "+f"(d[0]), "+f"(d[1]), "+f"(d[2]), "+f"(d[3])
        : "r"(a[0]), "r"(a[1]), "r"(a[2]), "r"(a[3]), "r"(b[0]), "r"(b[1]));
}

#define SW(o) ((o) ^ (((o) >> 3) & 0x70))   // SW128 byte swizzle within 1KB atom

// ---------------- fp16 mma.sync GEMM with cp.async pipeline -------------------
// C[M,N] = act(A[M,K] @ Bt[N,K]^T + bias),  A/Bt/C fp16, bias fp32, accum fp32.
// Tiles: BM=128, BN=192, BK=64 halves (128B rows, SW128).
// 8 warps: 2M x 4N, warp tile 64x48 (4 m-frags x 6 n-frags, 96 acc regs).
// GATHER=1: A row e = concat(emb[src[e]], emb[dst[e]], yp[batch[src[e]]]).
#define BM 128
#define BN 192
#define BK 64
#define A_TILE_BYTES 16384                 // 128 rows * 128B
#define B_TILE_BYTES 24576                 // 192 rows * 128B
#define STAGE_BYTES (A_TILE_BYTES + B_TILE_BYTES)   // 40 KB
#define NSTAGE 3
#define DYN_BYTES (NSTAGE * STAGE_BYTES)   // 120 KB

template<int GATHER>
__global__ __launch_bounds__(256, 1) void mma_gemm(
    const __half* __restrict__ A, int lda,
    const __half* __restrict__ Bt,
    const float* __restrict__ bias,
    __half* __restrict__ C, int ldc,
    int M, int K, int act,
    const __half* __restrict__ emb, const __half* __restrict__ yp,
    const int* __restrict__ edge_index, const int* __restrict__ batch)
{
    extern __shared__ char sh[];
    __shared__ int sSrc[128], sDst[128], sG[128];

    const int tid = threadIdx.x;
    const int wid = tid >> 5, lane = tid & 31;
    const int g = lane >> 2, t = lane & 3;
    const int wm = wid & 1, wn = wid >> 1;      // 2 M-warps x 4 N-warps
    const int m0 = blockIdx.y * BM;
    const int n0 = blockIdx.x * BN;

    if (GATHER) {
        if (tid < 128) {
            int e = m0 + tid; if (e >= M) e = 0;
            int s = edge_index[e];
            sSrc[tid] = s;
            sDst[tid] = edge_index[M + e];
            sG[tid]   = batch[s];
        }
        __syncthreads();
    }

    const int nk = K / BK;
    const uint32_t shbase = smem_u32(sh);

    // loader: A = 1024 16B-chunks (4/thread), B = 1536 (6/thread)
    const int lrow0 = tid >> 3;           // +32*i
    const int lchB  = (tid & 7) * 16;     // byte chunk in 128B row
    const int lchH  = (tid & 7) * 8;      // same, in halves

    auto issue_tile = [&](int kt) {
        if (kt < nk) {
            uint32_t As = shbase + (uint32_t)(kt % NSTAGE) * STAGE_BYTES;
            uint32_t Bs = As + A_TILE_BYTES;
            #pragma unroll
            for (int i = 0; i < 4; i++) {
                int row = lrow0 + i * 32;
                uint32_t da = As + SW((uint32_t)(row * 128 + lchB));
                if (!GATHER) {
                    int gr = m0 + row;
                    cp_async16(da, A + (long long)gr * lda + kt * BK + lchH, gr < M);
                } else {
                    int seg = (kt * BK) / DD;
                    int off = kt * BK - seg * DD + lchH;
                    const __half* base;
                    if (seg == 0)      base = emb + (long long)sSrc[row] * DD;
                    else if (seg == 1) base = emb + (long long)sDst[row] * DD;
                    else               base = yp  + (long long)sG[row]   * DD;
                    cp_async16(da, base + off, true);
                }
            }
            #pragma unroll
            for (int i = 0; i < 6; i++) {
                int row = lrow0 + i * 32;     // 0..191
                uint32_t db = Bs + SW((uint32_t)(row * 128 + lchB));
                cp_async16(db, Bt + (long long)(n0 + row) * K + kt * BK + lchH, true);
            }
        }
        CP_COMMIT();
    };

    float acc[4][6][4];
    #pragma unroll
    for (int i = 0; i < 4; i++)
        #pragma unroll
        for (int j = 0; j < 6; j++)
            #pragma unroll
            for (int q = 0; q < 4; q++) acc[i][j][q] = 0.f;

    issue_tile(0);
    issue_tile(1);

    const int lmRow = lane & 15;                 // row within 16-row group
    const int lmHi  = (lane & 16) ? 16 : 0;      // k-hi 16B chunk

    #pragma unroll 1
    for (int kt = 0; kt < nk; ++kt) {
        CP_WAIT(1);
        __syncthreads();
        issue_tile(kt + 2);

        uint32_t As = shbase + (uint32_t)(kt % NSTAGE) * STAGE_BYTES;
        uint32_t Bs = As + A_TILE_BYTES;

        #pragma unroll
        for (int ks = 0; ks < 4; ++ks) {         // 4 x k16 sections
            const int kb = ks * 32 + lmHi;
            uint32_t a[4][4], b[6][2];
            #pragma unroll
            for (int mt = 0; mt < 4; ++mt) {
                int row = wm * 64 + mt * 16 + lmRow;
                ldsm_x4(a[mt][0], a[mt][1], a[mt][2], a[mt][3],
                        As + SW((uint32_t)(row * 128 + kb)));
            }
            #pragma unroll
            for (int nq = 0; nq < 3; ++nq) {     // each covers 2 n8 fragments
                int row = wn * 48 + nq * 16 + lmRow;
                ldsm_x4(b[2*nq][0], b[2*nq+1][0], b[2*nq][1], b[2*nq+1][1],
                        Bs + SW((uint32_t)(row * 128 + kb)));
            }
            #pragma unroll
            for (int mt = 0; mt < 4; ++mt)
                #pragma unroll
                for (int nt = 0; nt < 6; ++nt)
                    mma_f16(acc[mt][nt], a[mt], b[nt]);
        }
    }

    // ---- epilogue: bias + activation + fp16 store ----
    #pragma unroll
    for (int mt = 0; mt < 4; ++mt) {
        int row0 = m0 + wm * 64 + mt * 16 + g;
        #pragma unroll
        for (int nt = 0; nt < 6; ++nt) {
            int col = n0 + wn * 48 + nt * 8 + t * 2;
            float2 bb = *(const float2*)(bias + col);
            float v0 = acc[mt][nt][0] + bb.x;
            float v1 = acc[mt][nt][1] + bb.y;
            float v2 = acc[mt][nt][2] + bb.x;
            float v3 = acc[mt][nt][3] + bb.y;
            if (act == 1) {
                v0 = fmaxf(v0, 0.f); v1 = fmaxf(v1, 0.f);
                v2 = fmaxf(v2, 0.f); v3 = fmaxf(v3, 0.f);
            } else if (act == 2) {
                v0 = (v0 > 0.f) ? v0 : 0.4f * v0;  v1 = (v1 > 0.f) ? v1 : 0.4f * v1;
                v2 = (v2 > 0.f) ? v2 : 0.4f * v2;  v3 = (v3 > 0.f) ? v3 : 0.4f * v3;
            }
            if (row0 < M)
                *(__half2*)(C + (long long)row0 * ldc + col) =
                    __float22half2_rn(make_float2(v0, v1));
            if (row0 + 8 < M)
                *(__half2*)(C + (long long)(row0 + 8) * ldc + col) =
                    __float22half2_rn(make_float2(v2, v3));
        }
    }
}

// ---------------- batched prep kernels ----------------------------------------
struct Ptr6 { const float* p[6]; };
struct Ptr2 { const float* p[2]; };

// 6x 768x768 transposes: Wt[n*768 + k] = W[k*768 + n], fp16 out
__global__ __launch_bounds__(256) void transpose6(Ptr6 src, __half* dstBase)
{
    const float* W = src.p[blockIdx.z];
    __half* Wt = dstBase + (size_t)blockIdx.z * ((size_t)DD * DD);
    __shared__ float tb[32][33];
    int n0 = blockIdx.x * 32, k0 = blockIdx.y * 32;
    int x = threadIdx.x & 31, y = threadIdx.x >> 5;
    #pragma unroll
    for (int i = 0; i < 32; i += 8)
        tb[y + i][x] = W[(long long)(k0 + y + i) * DD + n0 + x];
    __syncthreads();
    #pragma unroll
    for (int i = 0; i < 32; i += 8)
        Wt[(long long)(n0 + y + i) * DD + k0 + x] = __float2half_rn(tb[x][y + i]);
}

// 2x 2304x768 transposes: Wt[n*2304 + k] = W[k*768 + n]
__global__ __launch_bounds__(256) void transpose2(Ptr2 src, __half* dstBase)
{
    const float* W = src.p[blockIdx.z];
    __half* Wt = dstBase + (size_t)blockIdx.z * ((size_t)D3 * DD);
    __shared__ float tb[32][33];
    int n0 = blockIdx.x * 32, k0 = blockIdx.y * 32;
    int x = threadIdx.x & 31, y = threadIdx.x >> 5;
    #pragma unroll
    for (int i = 0; i < 32; i += 8)
        tb[y + i][x] = W[(long long)(k0 + y + i) * DD + n0 + x];
    __syncthreads();
    #pragma unroll
    for (int i = 0; i < 32; i += 8)
        Wt[(long long)(n0 + y + i) * D3 + k0 + x] = __float2half_rn(tb[x][y + i]);
}

// x and y fp32->fp16 in one launch
__global__ __launch_bounds__(256) void convert_xy(
    const float* __restrict__ x, const float* __restrict__ y,
    __half* __restrict__ xh, __half* __restrict__ yh)
{
    const long long nx = (long long)NN * DD;
    const long long ny = (long long)GG * DD;
    long long i = ((long long)blockIdx.x * 256 + threadIdx.x) * 4;
    const float* src; __half* dst; long long j;
    if (i < nx) { src = x; dst = xh; j = i; }
    else if (i < nx + ny) { src = y; dst = yh; j = i - nx; }
    else return;
    float4 v = *(const float4*)(src + j);
    *(__half2*)(dst + j)     = __float22half2_rn(make_float2(v.x, v.y));
    *(__half2*)(dst + j + 2) = __float22half2_rn(make_float2(v.z, v.w));
}

// ---------------- final head: sigmoid(qh @ pc2_W + pc2_b), std copy ---------
__global__ __launch_bounds__(256) void final_head(
    const __half* __restrict__ qh, const float* __restrict__ W /*[768,2]*/,
    const float* __restrict__ b2, const float* __restrict__ lab,
    float* __restrict__ out, int E)
{
    __shared__ float w0[DD];
    __shared__ float w1[DD];
    for (int i = threadIdx.x; i < DD; i += blockDim.x) {
        w0[i] = W[2 * i];
        w1[i] = W[2 * i + 1];
    }
    __syncthreads();

    int warp = threadIdx.x >> 5;
    int lane = threadIdx.x & 31;
    int e = blockIdx.x * 8 + warp;
    if (e >= E) return;

    const __half2* row = (const __half2*)(qh + (long long)e * DD);
    float a0 = 0.f, a1 = 0.f;
    #pragma unroll 4
    for (int k = lane; k < DD / 2; k += 32) {
        float2 f = __half22float2(row[k]);
        a0 = fmaf(f.x, w0[2*k], a0);   a0 = fmaf(f.y, w0[2*k+1], a0);
        a1 = fmaf(f.x, w1[2*k], a1);   a1 = fmaf(f.y, w1[2*k+1], a1);
    }
    #pragma unroll
    for (int off = 16; off > 0; off >>= 1) {
        a0 += __shfl_xor_sync(0xffffffffu, a0, off);
        a1 += __shfl_xor_sync(0xffffffffu, a1, off);
    }
    if (lane == 0) {
        out[2 * e]     = 1.f / (1.f + expf(-(a0 + b2[0])));
        out[2 * e + 1] = 1.f / (1.f + expf(-(a1 + b2[1])));
        out[2 * E + e] = lab[e];
    }
}

// ---------------- host launch ------------------------------------------------
static __half *p_xh = nullptr, *p_h0 = nullptr, *p_emb3 = nullptr, *p_emb = nullptr,
              *p_yh = nullptr, *p_yp = nullptr, *p_qh = nullptr, *p_wT = nullptr;

extern "C" void kernel_launch(void* const* d_in, const int* in_sizes, int n_in,
                              void* d_out, int out_size)
{
    if (!p_h0) {  // one-time setup on the (uncaptured) correctness call
        cudaGetSymbolAddress((void**)&p_xh,   g_xh);
        cudaGetSymbolAddress((void**)&p_h0,   g_h0);
        cudaGetSymbolAddress((void**)&p_emb3, g_emb3);
        cudaGetSymbolAddress((void**)&p_emb,  g_emb);
        cudaGetSymbolAddress((void**)&p_yh,   g_yh);
        cudaGetSymbolAddress((void**)&p_yp,   g_yp);
        cudaGetSymbolAddress((void**)&p_qh,   g_qh);
        cudaGetSymbolAddress((void**)&p_wT,   g_wT);
        cudaFuncSetAttribute(mma_gemm<0>, cudaFuncAttributeMaxDynamicSharedMemorySize, DYN_BYTES);
        cudaFuncSetAttribute(mma_gemm<1>, cudaFuncAttributeMaxDynamicSharedMemorySize, DYN_BYTES);
    }

    const float* x          = (const float*)d_in[0];
    const int*   edge_index = (const int*  )d_in[1];
    const int*   batch      = (const int*  )d_in[2];
    const float* y          = (const float*)d_in[5];
    const float* edge_label = (const float*)d_in[6];
    const float* ah_W  = (const float*)d_in[7];
    const float* ah_b  = (const float*)d_in[8];
    const float* c0_W  = (const float*)d_in[9];
    const float* c0_b  = (const float*)d_in[10];
    const float* c1_W  = (const float*)d_in[11];
    const float* c1_b  = (const float*)d_in[12];
    const float* c2_W  = (const float*)d_in[13];
    const float* c2_b  = (const float*)d_in[14];
    const float* o1_W  = (const float*)d_in[15];
    const float* o1_b  = (const float*)d_in[16];
    const float* o2_W  = (const float*)d_in[17];
    const float* o2_b  = (const float*)d_in[18];
    const float* py_W  = (const float*)d_in[19];
    const float* py_b  = (const float*)d_in[20];
    const float* pc1_W = (const float*)d_in[21];
    const float* pc1_b = (const float*)d_in[22];
    const float* pc2_W = (const float*)d_in[23];
    const float* pc2_b = (const float*)d_in[24];

    float* out = (float*)d_out;

    const long long S = (long long)DD * DD;        // 589824
    const long long L = (long long)D3 * DD;        // 1769472
    __half* wt_ah  = p_wT;                         // slots 0..5: 768x768
    __half* wt_c0  = p_wT + S;
    __half* wt_c1  = p_wT + 2 * S;
    __half* wt_c2  = p_wT + 3 * S;
    __half* wt_o2  = p_wT + 4 * S;
    __half* wt_py  = p_wT + 5 * S;
    __half* wt_o1  = p_wT + 6 * S;                 // slots 6,7: 2304-K
    __half* wt_pc1 = p_wT + 6 * S + L;

    // ---- prep (3 launches) ----
    {
        Ptr6 s6; s6.p[0] = ah_W; s6.p[1] = c0_W; s6.p[2] = c1_W;
                 s6.p[3] = c2_W; s6.p[4] = o2_W; s6.p[5] = py_W;
        transpose6<<<dim3(DD/32, DD/32, 6), 256>>>(s6, p_wT);
        Ptr2 s2; s2.p[0] = o1_W; s2.p[1] = pc1_W;
        transpose2<<<dim3(DD/32, D3/32, 2), 256>>>(s2, p_wT + 6 * S);
        long long tot = ((long long)NN * DD + (long long)GG * DD) / 4;
        convert_xy<<<(unsigned)((tot + 255) / 256), 256>>>(x, y, p_xh, p_yh);
    }

    dim3 blk(256);
    dim3 gN(DD / BN, (NN + BM - 1) / BM);   // 4 x 313
    dim3 gE(DD / BN, (EE + BM - 1) / BM);   // 4 x 782
    dim3 gG(DD / BN, 1);

    // Encoder
    mma_gemm<0><<<gN, blk, DYN_BYTES>>>(p_xh, DD, wt_ah, ah_b, p_h0, DD, NN, DD, 1,
                                        nullptr, nullptr, nullptr, nullptr);
    mma_gemm<0><<<gN, blk, DYN_BYTES>>>(p_h0, DD, wt_c0, c0_b, p_emb3, D3, NN, DD, 1,
                                        nullptr, nullptr, nullptr, nullptr);
    mma_gemm<0><<<gN, blk, DYN_BYTES>>>(p_emb3, D3, wt_c1, c1_b, p_emb3 + DD, D3, NN, DD, 1,
                                        nullptr, nullptr, nullptr, nullptr);
    mma_gemm<0><<<gN, blk, DYN_BYTES>>>(p_emb3 + DD, D3, wt_c2, c2_b, p_emb3 + 2 * DD, D3, NN, DD, 1,
                                        nullptr, nullptr, nullptr, nullptr);
    mma_gemm<0><<<gN, blk, DYN_BYTES>>>(p_emb3, D3, wt_o1, o1_b, p_h0, DD, NN, D3, 1,
                                        nullptr, nullptr, nullptr, nullptr);
    mma_gemm<0><<<gN, blk, DYN_BYTES>>>(p_h0, DD, wt_o2, o2_b, p_emb, DD, NN, DD, 0,
                                        nullptr, nullptr, nullptr, nullptr);
    // yp (per-graph, G=128 rows)
    mma_gemm<0><<<gG, blk, DYN_BYTES>>>(p_yh, DD, wt_py, py_b, p_yp, DD, GG, DD, 2,
                                        nullptr, nullptr, nullptr, nullptr);
    // qh = relu(concat(emb[src], emb[dst], yp[batch[src]]) @ pc1 + b) — gather fused
    mma_gemm<1><<<gE, blk, DYN_BYTES>>>(nullptr, 0, wt_pc1, pc1_b, p_qh, DD, EE, D3, 1,
                                        p_emb, p_yp, edge_index, batch);
    // pred = sigmoid(qh @ pc2 + b); std = edge_label
    final_head<<<(EE + 7) / 8, 256>>>(p_qh, pc2_W, pc2_b, edge_label, out, EE);

    (void)n_in; (void)in_sizes; (void)out_size;
}

// round 7
// speedup vs baseline: 1.6761x; 1.6761x over previous
#include <cuda_runtime.h>
#include <cuda_fp16.h>
#include <cstdint>
#include <math.h>

// Problem shapes (fixed by setup_inputs)
#define NN 40000
#define EE 100000
#define DD 768
#define GG 128
#define D3 2304

// ---------------- scratch (static device globals; allocation-free) ----------
__device__ static __half g_xh [(size_t)NN * DD];        // x in fp16
__device__ static __half g_h0 [(size_t)NN * DD];        // h0 / t
__device__ static __half g_emb3[(size_t)NN * D3];       // concat(h1,h2,h3)
__device__ static __half g_uv [(size_t)NN * 2 * DD];    // [u | v] per node
__device__ static __half g_yh [(size_t)GG * DD];        // y in fp16
__device__ static __half g_yp [(size_t)GG * DD];        // leaky(y@py+b)
__device__ static __half g_w  [(size_t)GG * DD];        // yp@W3 + pc1_b per graph
__device__ static __half g_wT [8257536];                // weights: 14 * 768*768 halves
__device__ static float  g_buv[2 * DD];                 // bias for uv GEMM
__device__ static float  g_zero[DD];                    // zero bias (device globals zero-init)

// ---------------- helpers ----------------------------------------------------
__device__ __forceinline__ uint32_t smem_u32(const void* p) {
    uint32_t a;
    asm("{ .reg .u64 t; cvta.to.shared.u64 t, %1; cvt.u32.u64 %0, t; }" : "=r"(a) : "l"(p));
    return a;
}

__device__ __forceinline__ void cp_async16(uint32_t dst, const void* src, bool pred) {
    int sz = pred ? 16 : 0;
    asm volatile("cp.async.cg.shared.global [%0], [%1], 16, %2;"
                 :: "r"(dst), "l"(src), "r"(sz) : "memory");
}
#define CP_COMMIT() asm volatile("cp.async.commit_group;" ::: "memory")
#define CP_WAIT(n)  asm volatile("cp.async.wait_group %0;" :: "n"(n) : "memory")

__device__ __forceinline__ void ldsm_x4(uint32_t& r0, uint32_t& r1, uint32_t& r2, uint32_t& r3,
                                        uint32_t addr) {
    asm volatile("ldmatrix.sync.aligned.m8n8.x4.shared.b16 {%0,%1,%2,%3}, [%4];"
                 : "=r"(r0), "=r"(r1), "=r"(r2), "=r"(r3) : "r"(addr));
}

__device__ __forceinline__ void mma_f16(float d[4], const uint32_t a[4], const uint32_t b[2]) {
    asm volatile(
        "mma.sync.aligned.m16n8k16.row.col.f32.f16.f16.f32 "
        "{%0,%1,%2,%3}, {%4,%5,%6,%7}, {%8,%9}, {%0,%1,%2,%3};"
        : "+f"(d[0]), "+f"(d[1]), "+f"(d[2]), "+f"(d[3])
        : "r"(a[0]), "r"(a[1]), "r"(a[2]), "r"(a[3]), "r"(b[0]), "r"(b[1]));
}

#define SW(o) ((o) ^ (((o) >> 3) & 0x70))   // SW128 byte swizzle within 1KB atom

// ---------------- fp16 mma.sync GEMM (R5 proven config) -----------------------
// C[M,N] = act(A[M,K] @ Bt[N,K]^T + bias),  A/Bt/C fp16, bias fp32, accum fp32.
// BM=128, BN=128, BK=64 halves (128B rows, SW128). 8 warps: 4M x 2N (32x64 tile).
#define BM 128
#define BN 128
#define BK 64
#define TILE_BYTES 16384                   // 128 rows * 128B
#define STAGE_BYTES (2 * TILE_BYTES)       // A then B: 32 KB
#define NSTAGE 3
#define DYN_BYTES (NSTAGE * STAGE_BYTES)   // 96 KB -> 2 CTAs/SM

__global__ __launch_bounds__(256) void mma_gemm(
    const __half* __restrict__ A, int lda,
    const __half* __restrict__ Bt,
    const float* __restrict__ bias,
    __half* __restrict__ C, int ldc,
    int M, int K, int act)
{
    extern __shared__ char sh[];

    const int tid = threadIdx.x;
    const int wid = tid >> 5, lane = tid & 31;
    const int g = lane >> 2, t = lane & 3;
    const int wm = wid & 3, wn = wid >> 2;      // 4 M-warps x 2 N-warps
    const int m0 = blockIdx.y * BM;
    const int n0 = blockIdx.x * BN;

    const int nk = K / BK;
    const uint32_t shbase = smem_u32(sh);

    const int lrow0 = tid >> 3;           // +32*i
    const int lchB  = (tid & 7) * 16;
    const int lchH  = (tid & 7) * 8;

    auto issue_tile = [&](int kt) {
        if (kt < nk) {
            uint32_t As = shbase + (uint32_t)(kt % NSTAGE) * STAGE_BYTES;
            uint32_t Bs = As + TILE_BYTES;
            #pragma unroll
            for (int i = 0; i < 4; i++) {
                int row = lrow0 + i * 32;
                int gr = m0 + row;
                cp_async16(As + SW((uint32_t)(row * 128 + lchB)),
                           A + (long long)gr * lda + kt * BK + lchH, gr < M);
                cp_async16(Bs + SW((uint32_t)(row * 128 + lchB)),
                           Bt + (long long)(n0 + row) * K + kt * BK + lchH, true);
            }
        }
        CP_COMMIT();
    };

    float acc[2][8][4];
    #pragma unroll
    for (int i = 0; i < 2; i++)
        #pragma unroll
        for (int j = 0; j < 8; j++)
            #pragma unroll
            for (int q = 0; q < 4; q++) acc[i][j][q] = 0.f;

    issue_tile(0);
    issue_tile(1);

    const int lmRow = lane & 15;
    const int lmHi  = (lane & 16) ? 16 : 0;

    #pragma unroll 1
    for (int kt = 0; kt < nk; ++kt) {
        CP_WAIT(1);
        __syncthreads();
        issue_tile(kt + 2);

        uint32_t As = shbase + (uint32_t)(kt % NSTAGE) * STAGE_BYTES;
        uint32_t Bs = As + TILE_BYTES;

        #pragma unroll
        for (int ks = 0; ks < 4; ++ks) {
            const int kb = ks * 32 + lmHi;
            uint32_t a[2][4], b[8][2];
            #pragma unroll
            for (int mt = 0; mt < 2; ++mt) {
                int row = wm * 32 + mt * 16 + lmRow;
                ldsm_x4(a[mt][0], a[mt][1], a[mt][2], a[mt][3],
                        As + SW((uint32_t)(row * 128 + kb)));
            }
            #pragma unroll
            for (int nq = 0; nq < 4; ++nq) {
                int row = wn * 64 + nq * 16 + lmRow;
                ldsm_x4(b[2*nq][0], b[2*nq+1][0], b[2*nq][1], b[2*nq+1][1],
                        Bs + SW((uint32_t)(row * 128 + kb)));
            }
            #pragma unroll
            for (int mt = 0; mt < 2; ++mt)
                #pragma unroll
                for (int nt = 0; nt < 8; ++nt)
                    mma_f16(acc[mt][nt], a[mt], b[nt]);
        }
    }

    // ---- epilogue: bias + activation + fp16 store ----
    #pragma unroll
    for (int mt = 0; mt < 2; ++mt) {
        int row0 = m0 + wm * 32 + mt * 16 + g;
        #pragma unroll
        for (int nt = 0; nt < 8; ++nt) {
            int col = n0 + wn * 64 + nt * 8 + t * 2;
            float2 bb = *(const float2*)(bias + col);
            float v0 = acc[mt][nt][0] + bb.x;
            float v1 = acc[mt][nt][1] + bb.y;
            float v2 = acc[mt][nt][2] + bb.x;
            float v3 = acc[mt][nt][3] + bb.y;
            if (act == 1) {
                v0 = fmaxf(v0, 0.f); v1 = fmaxf(v1, 0.f);
                v2 = fmaxf(v2, 0.f); v3 = fmaxf(v3, 0.f);
            } else if (act == 2) {
                v0 = (v0 > 0.f) ? v0 : 0.4f * v0;  v1 = (v1 > 0.f) ? v1 : 0.4f * v1;
                v2 = (v2 > 0.f) ? v2 : 0.4f * v2;  v3 = (v3 > 0.f) ? v3 : 0.4f * v3;
            }
            if (row0 < M)
                *(__half2*)(C + (long long)row0 * ldc + col) =
                    __float22half2_rn(make_float2(v0, v1));
            if (row0 + 8 < M)
                *(__half2*)(C + (long long)(row0 + 8) * ldc + col) =
                    __float22half2_rn(make_float2(v2, v3));
        }
    }
}

// ---------------- batched prep kernels ----------------------------------------
struct Ptr8 { const float* p[8]; };

// 8x 768x768 transposes: Wt[n*768 + k] = W[k*768 + n], fp16 out
__global__ __launch_bounds__(256) void transpose8(Ptr8 src, __half* dstBase)
{
    const float* W = src.p[blockIdx.z];
    __half* Wt = dstBase + (size_t)blockIdx.z * ((size_t)DD * DD);
    __shared__ float tb[32][33];
    int n0 = blockIdx.x * 32, k0 = blockIdx.y * 32;
    int x = threadIdx.x & 31, y = threadIdx.x >> 5;
    #pragma unroll
    for (int i = 0; i < 32; i += 8)
        tb[y + i][x] = W[(long long)(k0 + y + i) * DD + n0 + x];
    __syncthreads();
    #pragma unroll
    for (int i = 0; i < 32; i += 8)
        Wt[(long long)(n0 + y + i) * DD + k0 + x] = __float2half_rn(tb[x][y + i]);
}

// o1 transpose: [2304(K) x 768(N)] -> Wt[n*2304 + k]
__global__ __launch_bounds__(256) void transpose_o1(
    const float* __restrict__ W, __half* __restrict__ Wt)
{
    __shared__ float tb[32][33];
    int n0 = blockIdx.x * 32, k0 = blockIdx.y * 32;
    int x = threadIdx.x & 31, y = threadIdx.x >> 5;
    #pragma unroll
    for (int i = 0; i < 32; i += 8)
        tb[y + i][x] = W[(long long)(k0 + y + i) * DD + n0 + x];
    __syncthreads();
    #pragma unroll
    for (int i = 0; i < 32; i += 8)
        Wt[(long long)(n0 + y + i) * D3 + k0 + x] = __float2half_rn(tb[x][y + i]);
}

// fp32->fp16 flat convert of x, y, o2_W into xh, yh, o2h
__global__ __launch_bounds__(256) void convert_all(
    const float* __restrict__ x, const float* __restrict__ y,
    const float* __restrict__ o2W,
    __half* __restrict__ xh, __half* __restrict__ yh, __half* __restrict__ o2h)
{
    const long long nx = (long long)NN * DD;
    const long long ny = (long long)GG * DD;
    const long long nw = (long long)DD * DD;
    long long i = ((long long)blockIdx.x * 256 + threadIdx.x) * 4;
    const float* src; __half* dst; long long j;
    if (i < nx) { src = x; dst = xh; j = i; }
    else if (i < nx + ny) { src = y; dst = yh; j = i - nx; }
    else if (i < nx + ny + nw) { src = o2W; dst = o2h; j = i - nx - ny; }
    else return;
    float4 v = *(const float4*)(src + j);
    *(__half2*)(dst + j)     = __float22half2_rn(make_float2(v.x, v.y));
    *(__half2*)(dst + j + 2) = __float22half2_rn(make_float2(v.z, v.w));
}

// b_uv[n] = sum_k o2_b[k] * W{1|2}[k,n]  (reads wt_W1/wt_W2, i.e. [n,k] layout)
__global__ __launch_bounds__(256) void bias_uv(
    const __half* __restrict__ wt_W1, const __half* __restrict__ wt_W2,
    const float* __restrict__ o2_b, float* __restrict__ buv)
{
    int n = blockIdx.x * 256 + threadIdx.x;   // 0..1535
    if (n >= 2 * DD) return;
    const __half* wrow = (n < DD) ? (wt_W1 + (long long)n * DD)
                                  : (wt_W2 + (long long)(n - DD) * DD);
    float s = 0.f;
    #pragma unroll 8
    for (int k = 0; k < DD; k++)
        s = fmaf(__half2float(wrow[k]), o2_b[k], s);
    buv[n] = s;
}

// ---------------- fused edge head ---------------------------------------------
// per edge: q = relu(u[src] + v[dst] + w[batch[src]]); pred = sigmoid(q@pc2 + b2)
__global__ __launch_bounds__(256) void edge_head(
    const __half* __restrict__ uv, const __half* __restrict__ w,
    const int* __restrict__ edge_index, const int* __restrict__ batch,
    const float* __restrict__ pc2W /*[768,2]*/, const float* __restrict__ b2,
    const float* __restrict__ lab, float* __restrict__ out, int E)
{
    __shared__ float w0[DD];
    __shared__ float w1[DD];
    for (int i = threadIdx.x; i < DD; i += blockDim.x) {
        w0[i] = pc2W[2 * i];
        w1[i] = pc2W[2 * i + 1];
    }
    __syncthreads();

    int warp = threadIdx.x >> 5;
    int lane = threadIdx.x & 31;
    int e = blockIdx.x * 8 + warp;
    if (e >= E) return;

    int src = edge_index[e];
    int dst = edge_index[E + e];
    int gph = batch[src];

    const __half2* ur = (const __half2*)(uv + (long long)src * (2 * DD));
    const __half2* vr = (const __half2*)(uv + (long long)dst * (2 * DD) + DD);
    const __half2* wr = (const __half2*)(w  + (long long)gph * DD);

    float a0 = 0.f, a1 = 0.f;
    #pragma unroll
    for (int i = 0; i < 12; i++) {
        int k = lane + i * 32;               // half2 index, 0..383
        float2 fu = __half22float2(ur[k]);
        float2 fv = __half22float2(vr[k]);
        float2 fw = __half22float2(wr[k]);
        float q0 = fmaxf(fu.x + fv.x + fw.x, 0.f);
        float q1 = fmaxf(fu.y + fv.y + fw.y, 0.f);
        a0 = fmaf(q0, w0[2*k], a0);   a0 = fmaf(q1, w0[2*k+1], a0);
        a1 = fmaf(q0, w1[2*k], a1);   a1 = fmaf(q1, w1[2*k+1], a1);
    }
    #pragma unroll
    for (int off = 16; off > 0; off >>= 1) {
        a0 += __shfl_xor_sync(0xffffffffu, a0, off);
        a1 += __shfl_xor_sync(0xffffffffu, a1, off);
    }
    if (lane == 0) {
        out[2 * e]     = 1.f / (1.f + expf(-(a0 + b2[0])));
        out[2 * e + 1] = 1.f / (1.f + expf(-(a1 + b2[1])));
        out[2 * E + e] = lab[e];
    }
}

// ---------------- host launch ------------------------------------------------
static __half *p_xh = nullptr, *p_h0 = nullptr, *p_emb3 = nullptr, *p_uv = nullptr,
              *p_yh = nullptr, *p_yp = nullptr, *p_w = nullptr, *p_wT = nullptr;
static float  *p_buv = nullptr, *p_zero = nullptr;

extern "C" void kernel_launch(void* const* d_in, const int* in_sizes, int n_in,
                              void* d_out, int out_size)
{
    if (!p_h0) {  // one-time setup on the (uncaptured) correctness call
        cudaGetSymbolAddress((void**)&p_xh,   g_xh);
        cudaGetSymbolAddress((void**)&p_h0,   g_h0);
        cudaGetSymbolAddress((void**)&p_emb3, g_emb3);
        cudaGetSymbolAddress((void**)&p_uv,   g_uv);
        cudaGetSymbolAddress((void**)&p_yh,   g_yh);
        cudaGetSymbolAddress((void**)&p_yp,   g_yp);
        cudaGetSymbolAddress((void**)&p_w,    g_w);
        cudaGetSymbolAddress((void**)&p_wT,   g_wT);
        cudaGetSymbolAddress((void**)&p_buv,  g_buv);
        cudaGetSymbolAddress((void**)&p_zero, g_zero);
        cudaFuncSetAttribute(mma_gemm, cudaFuncAttributeMaxDynamicSharedMemorySize, DYN_BYTES);
    }

    const float* x          = (const float*)d_in[0];
    const int*   edge_index = (const int*  )d_in[1];
    const int*   batch      = (const int*  )d_in[2];
    const float* y          = (const float*)d_in[5];
    const float* edge_label = (const float*)d_in[6];
    const float* ah_W  = (const float*)d_in[7];
    const float* ah_b  = (const float*)d_in[8];
    const float* c0_W  = (const float*)d_in[9];
    const float* c0_b  = (const float*)d_in[10];
    const float* c1_W  = (const float*)d_in[11];
    const float* c1_b  = (const float*)d_in[12];
    const float* c2_W  = (const float*)d_in[13];
    const float* c2_b  = (const float*)d_in[14];
    const float* o1_W  = (const float*)d_in[15];
    const float* o1_b  = (const float*)d_in[16];
    const float* o2_W  = (const float*)d_in[17];
    const float* o2_b  = (const float*)d_in[18];
    const float* py_W  = (const float*)d_in[19];
    const float* py_b  = (const float*)d_in[20];
    const float* pc1_W = (const float*)d_in[21];
    const float* pc1_b = (const float*)d_in[22];
    const float* pc2_W = (const float*)d_in[23];
    const float* pc2_b = (const float*)d_in[24];

    float* out = (float*)d_out;

    const long long S = (long long)DD * DD;        // 589824
    __half* wt_ah = p_wT;
    __half* wt_c0 = p_wT + S;
    __half* wt_c1 = p_wT + 2 * S;
    __half* wt_c2 = p_wT + 3 * S;
    __half* wt_py = p_wT + 4 * S;
    __half* wt_W1 = p_wT + 5 * S;
    __half* wt_W2 = p_wT + 6 * S;
    __half* wt_W3 = p_wT + 7 * S;
    __half* wt_o1 = p_wT + 8 * S;                  // [768, 2304]
    __half* wt_uv = p_wT + 11 * S;                 // composite [1536, 768]
    __half* o2h   = p_wT + 13 * S;                 // o2_W fp16 row-major

    // ---- prep ----
    {
        Ptr8 s8;
        s8.p[0] = ah_W; s8.p[1] = c0_W; s8.p[2] = c1_W; s8.p[3] = c2_W;
        s8.p[4] = py_W;
        s8.p[5] = pc1_W;                 // W1 = rows 0..767
        s8.p[6] = pc1_W + 768 * DD;      // W2
        s8.p[7] = pc1_W + 1536 * DD;     // W3
        transpose8<<<dim3(DD/32, DD/32, 8), 256>>>(s8, p_wT);
        transpose_o1<<<dim3(DD/32, D3/32), 256>>>(o1_W, wt_o1);
        long long tot = ((long long)NN * DD + (long long)GG * DD + (long long)DD * DD) / 4;
        convert_all<<<(unsigned)((tot + 255) / 256), 256>>>(x, y, o2_W, p_xh, p_yh, o2h);
        bias_uv<<<6, 256>>>(wt_W1, wt_W2, o2_b, p_buv);
        // composite weights: Bt_u[n,k] = sum_j W1[j,n] * o2_W[k,j]  (and W2 -> Bt_v)
        dim3 gC(DD / BN, DD / BM);    // 6 x 6
        mma_gemm<<<gC, 256, DYN_BYTES>>>(wt_W1, DD, o2h, p_zero, wt_uv,     DD, DD, DD, 0);
        mma_gemm<<<gC, 256, DYN_BYTES>>>(wt_W2, DD, o2h, p_zero, wt_uv + S, DD, DD, DD, 0);
    }

    dim3 blk(256);
    dim3 gN(DD / BN, (NN + BM - 1) / BM);        // 6 x 313
    dim3 gUV(2 * DD / BN, (NN + BM - 1) / BM);   // 12 x 313
    dim3 gG(DD / BN, 1);

    // Encoder
    mma_gemm<<<gN, blk, DYN_BYTES>>>(p_xh, DD, wt_ah, ah_b, p_h0, DD, NN, DD, 1);
    mma_gemm<<<gN, blk, DYN_BYTES>>>(p_h0, DD, wt_c0, c0_b, p_emb3, D3, NN, DD, 1);
    mma_gemm<<<gN, blk, DYN_BYTES>>>(p_emb3, D3, wt_c1, c1_b, p_emb3 + DD, D3, NN, DD, 1);
    mma_gemm<<<gN, blk, DYN_BYTES>>>(p_emb3 + DD, D3, wt_c2, c2_b, p_emb3 + 2 * DD, D3, NN, DD, 1);
    mma_gemm<<<gN, blk, DYN_BYTES>>>(p_emb3, D3, wt_o1, o1_b, p_h0, DD, NN, D3, 1);
    // uv = t @ [o2W*W1 | o2W*W2] + b_uv   (o2 folded; emb never materialized)
    mma_gemm<<<gUV, blk, DYN_BYTES>>>(p_h0, DD, wt_uv, p_buv, p_uv, 2 * DD, NN, DD, 0);
    // per-graph: yp = leaky(y@py + py_b); w = yp@W3 + pc1_b
    mma_gemm<<<gG, blk, DYN_BYTES>>>(p_yh, DD, wt_py, py_b, p_yp, DD, GG, DD, 2);
    mma_gemm<<<gG, blk, DYN_BYTES>>>(p_yp, DD, wt_W3, pc1_b, p_w, DD, GG, DD, 0);
    // fused edge head: relu(u+v+w) @ pc2 -> sigmoid -> out; std copy
    edge_head<<<(EE + 7) / 8, 256>>>(p_uv, p_w, edge_index, batch,
                                     pc2_W, pc2_b, edge_label, out, EE);

    (void)n_in; (void)in_sizes; (void)out_size;
}

// round 8
// speedup vs baseline: 1.8139x; 1.0822x over previous
#include <cuda_runtime.h>
#include <cuda_fp16.h>
#include <cstdint>
#include <math.h>

// Problem shapes (fixed by setup_inputs)
#define NN 40000
#define EE 100000
#define DD 768
#define GG 128
#define D3 2304

// ---------------- scratch (static device globals; allocation-free) ----------
__device__ static __half g_xh [(size_t)NN * DD];        // x in fp16
__device__ static __half g_h0 [(size_t)NN * DD];        // h0 / t
__device__ static __half g_emb3[(size_t)NN * D3];       // concat(h1,h2,h3)
__device__ static __half g_uv [(size_t)NN * 2 * DD];    // [u | v] per node
__device__ static __half g_yh [(size_t)GG * DD];        // y in fp16
__device__ static __half g_yp [(size_t)GG * DD];        // leaky(y@py+b)
__device__ static __half g_w  [(size_t)GG * DD];        // yp@W3 + pc1_b per graph
__device__ static __half g_wT [8257536];                // weights: 14 * 768*768 halves
__device__ static float  g_buv[2 * DD];                 // bias for uv GEMM
__device__ static float  g_zero[2 * DD];                // zero bias (device globals zero-init)

// ---------------- helpers ----------------------------------------------------
__device__ __forceinline__ uint32_t smem_u32(const void* p) {
    uint32_t a;
    asm("{ .reg .u64 t; cvta.to.shared.u64 t, %1; cvt.u32.u64 %0, t; }" : "=r"(a) : "l"(p));
    return a;
}

__device__ __forceinline__ void cp_async16(uint32_t dst, const void* src, bool pred) {
    int sz = pred ? 16 : 0;
    asm volatile("cp.async.cg.shared.global [%0], [%1], 16, %2;"
                 :: "r"(dst), "l"(src), "r"(sz) : "memory");
}
#define CP_COMMIT() asm volatile("cp.async.commit_group;" ::: "memory")
#define CP_WAIT(n)  asm volatile("cp.async.wait_group %0;" :: "n"(n) : "memory")

__device__ __forceinline__ void ldsm_x4(uint32_t& r0, uint32_t& r1, uint32_t& r2, uint32_t& r3,
                                        uint32_t addr) {
    asm volatile("ldmatrix.sync.aligned.m8n8.x4.shared.b16 {%0,%1,%2,%3}, [%4];"
                 : "=r"(r0), "=r"(r1), "=r"(r2), "=r"(r3) : "r"(addr));
}

__device__ __forceinline__ void mma_f16(float d[4], const uint32_t a[4], const uint32_t b[2]) {
    asm volatile(
        "mma.sync.aligned.m16n8k16.row.col.f32.f16.f16.f32 "
        "{%0,%1,%2,%3}, {%4,%5,%6,%7}, {%8,%9}, {%0,%1,%2,%3};"
        : "+f"(d[0]), "+f"(d[1]), "+f"(d[2]), "+f"(d[3])
        : "r"(a[0]), "r"(a[1]), "r"(a[2]), "r"(a[3]), "r"(b[0]), "r"(b[1]));
}

#define SW(o) ((o) ^ (((o) >> 3) & 0x70))   // SW128 byte swizzle within 1KB atom

// ---------------- fp16 mma.sync GEMM (R5 proven config) -----------------------
// C[M,N] = act(A[M,K] @ Bt[N,K]^T + bias),  A/Bt/C fp16, bias fp32, accum fp32.
// BM=128, BN=128, BK=64 halves (128B rows, SW128). 8 warps: 4M x 2N (32x64 tile).
#define BM 128
#define BN 128
#define BK 64
#define TILE_BYTES 16384                   // 128 rows * 128B
#define STAGE_BYTES (2 * TILE_BYTES)       // A then B: 32 KB
#define NSTAGE 3
#define DYN_BYTES (NSTAGE * STAGE_BYTES)   // 96 KB -> 2 CTAs/SM

__global__ __launch_bounds__(256) void mma_gemm(
    const __half* __restrict__ A, int lda,
    const __half* __restrict__ Bt,
    const float* __restrict__ bias,
    __half* __restrict__ C, int ldc,
    int M, int K, int act)
{
    extern __shared__ char sh[];

    const int tid = threadIdx.x;
    const int wid = tid >> 5, lane = tid & 31;
    const int g = lane >> 2, t = lane & 3;
    const int wm = wid & 3, wn = wid >> 2;      // 4 M-warps x 2 N-warps
    const int m0 = blockIdx.y * BM;
    const int n0 = blockIdx.x * BN;

    const int nk = K / BK;
    const uint32_t shbase = smem_u32(sh);

    const int lrow0 = tid >> 3;           // +32*i
    const int lchB  = (tid & 7) * 16;
    const int lchH  = (tid & 7) * 8;

    auto issue_tile = [&](int kt) {
        if (kt < nk) {
            uint32_t As = shbase + (uint32_t)(kt % NSTAGE) * STAGE_BYTES;
            uint32_t Bs = As + TILE_BYTES;
            #pragma unroll
            for (int i = 0; i < 4; i++) {
                int row = lrow0 + i * 32;
                int gr = m0 + row;
                cp_async16(As + SW((uint32_t)(row * 128 + lchB)),
                           A + (long long)gr * lda + kt * BK + lchH, gr < M);
                cp_async16(Bs + SW((uint32_t)(row * 128 + lchB)),
                           Bt + (long long)(n0 + row) * K + kt * BK + lchH, true);
            }
        }
        CP_COMMIT();
    };

    float acc[2][8][4];
    #pragma unroll
    for (int i = 0; i < 2; i++)
        #pragma unroll
        for (int j = 0; j < 8; j++)
            #pragma unroll
            for (int q = 0; q < 4; q++) acc[i][j][q] = 0.f;

    issue_tile(0);
    issue_tile(1);

    const int lmRow = lane & 15;
    const int lmHi  = (lane & 16) ? 16 : 0;

    #pragma unroll 1
    for (int kt = 0; kt < nk; ++kt) {
        CP_WAIT(1);
        __syncthreads();
        issue_tile(kt + 2);

        uint32_t As = shbase + (uint32_t)(kt % NSTAGE) * STAGE_BYTES;
        uint32_t Bs = As + TILE_BYTES;

        #pragma unroll
        for (int ks = 0; ks < 4; ++ks) {
            const int kb = ks * 32 + lmHi;
            uint32_t a[2][4], b[8][2];
            #pragma unroll
            for (int mt = 0; mt < 2; ++mt) {
                int row = wm * 32 + mt * 16 + lmRow;
                ldsm_x4(a[mt][0], a[mt][1], a[mt][2], a[mt][3],
                        As + SW((uint32_t)(row * 128 + kb)));
            }
            #pragma unroll
            for (int nq = 0; nq < 4; ++nq) {
                int row = wn * 64 + nq * 16 + lmRow;
                ldsm_x4(b[2*nq][0], b[2*nq+1][0], b[2*nq][1], b[2*nq+1][1],
                        Bs + SW((uint32_t)(row * 128 + kb)));
            }
            #pragma unroll
            for (int mt = 0; mt < 2; ++mt)
                #pragma unroll
                for (int nt = 0; nt < 8; ++nt)
                    mma_f16(acc[mt][nt], a[mt], b[nt]);
        }
    }

    // ---- epilogue: bias + activation + fp16 store ----
    #pragma unroll
    for (int mt = 0; mt < 2; ++mt) {
        int row0 = m0 + wm * 32 + mt * 16 + g;
        #pragma unroll
        for (int nt = 0; nt < 8; ++nt) {
            int col = n0 + wn * 64 + nt * 8 + t * 2;
            float2 bb = *(const float2*)(bias + col);
            float v0 = acc[mt][nt][0] + bb.x;
            float v1 = acc[mt][nt][1] + bb.y;
            float v2 = acc[mt][nt][2] + bb.x;
            float v3 = acc[mt][nt][3] + bb.y;
            if (act == 1) {
                v0 = fmaxf(v0, 0.f); v1 = fmaxf(v1, 0.f);
                v2 = fmaxf(v2, 0.f); v3 = fmaxf(v3, 0.f);
            } else if (act == 2) {
                v0 = (v0 > 0.f) ? v0 : 0.4f * v0;  v1 = (v1 > 0.f) ? v1 : 0.4f * v1;
                v2 = (v2 > 0.f) ? v2 : 0.4f * v2;  v3 = (v3 > 0.f) ? v3 : 0.4f * v3;
            }
            if (row0 < M)
                *(__half2*)(C + (long long)row0 * ldc + col) =
                    __float22half2_rn(make_float2(v0, v1));
            if (row0 + 8 < M)
                *(__half2*)(C + (long long)(row0 + 8) * ldc + col) =
                    __float22half2_rn(make_float2(v2, v3));
        }
    }
}

// ---------------- batched prep kernels ----------------------------------------
struct Ptr8 { const float* p[8]; };

// 8x 768x768 transposes: Wt[n*768 + k] = W[k*768 + n], fp16 out
__global__ __launch_bounds__(256) void transpose8(Ptr8 src, __half* dstBase)
{
    const float* W = src.p[blockIdx.z];
    __half* Wt = dstBase + (size_t)blockIdx.z * ((size_t)DD * DD);
    __shared__ float tb[32][33];
    int n0 = blockIdx.x * 32, k0 = blockIdx.y * 32;
    int x = threadIdx.x & 31, y = threadIdx.x >> 5;
    #pragma unroll
    for (int i = 0; i < 32; i += 8)
        tb[y + i][x] = W[(long long)(k0 + y + i) * DD + n0 + x];
    __syncthreads();
    #pragma unroll
    for (int i = 0; i < 32; i += 8)
        Wt[(long long)(n0 + y + i) * DD + k0 + x] = __float2half_rn(tb[x][y + i]);
}

// o1 transpose: [2304(K) x 768(N)] -> Wt[n*2304 + k]
__global__ __launch_bounds__(256) void transpose_o1(
    const float* __restrict__ W, __half* __restrict__ Wt)
{
    __shared__ float tb[32][33];
    int n0 = blockIdx.x * 32, k0 = blockIdx.y * 32;
    int x = threadIdx.x & 31, y = threadIdx.x >> 5;
    #pragma unroll
    for (int i = 0; i < 32; i += 8)
        tb[y + i][x] = W[(long long)(k0 + y + i) * DD + n0 + x];
    __syncthreads();
    #pragma unroll
    for (int i = 0; i < 32; i += 8)
        Wt[(long long)(n0 + y + i) * D3 + k0 + x] = __float2half_rn(tb[x][y + i]);
}

// fp32->fp16 flat convert of x, y, o2_W into xh, yh, o2h
__global__ __launch_bounds__(256) void convert_all(
    const float* __restrict__ x, const float* __restrict__ y,
    const float* __restrict__ o2W,
    __half* __restrict__ xh, __half* __restrict__ yh, __half* __restrict__ o2h)
{
    const long long nx = (long long)NN * DD;
    const long long ny = (long long)GG * DD;
    const long long nw = (long long)DD * DD;
    long long i = ((long long)blockIdx.x * 256 + threadIdx.x) * 4;
    const float* src; __half* dst; long long j;
    if (i < nx) { src = x; dst = xh; j = i; }
    else if (i < nx + ny) { src = y; dst = yh; j = i - nx; }
    else if (i < nx + ny + nw) { src = o2W; dst = o2h; j = i - nx - ny; }
    else return;
    float4 v = *(const float4*)(src + j);
    *(__half2*)(dst + j)     = __float22half2_rn(make_float2(v.x, v.y));
    *(__half2*)(dst + j + 2) = __float22half2_rn(make_float2(v.z, v.w));
}

// b_uv[n] = sum_k o2_b[k] * W12[n,k]  — one warp per n (wt_W1|wt_W2 contiguous)
__global__ __launch_bounds__(256) void bias_uv(
    const __half* __restrict__ wt_W12, const float* __restrict__ o2_b,
    float* __restrict__ buv)
{
    int gw = (blockIdx.x * 256 + threadIdx.x) >> 5;   // warp id = output n
    int lane = threadIdx.x & 31;
    if (gw >= 2 * DD) return;
    const __half2* wrow = (const __half2*)(wt_W12 + (long long)gw * DD);
    float s = 0.f;
    #pragma unroll
    for (int i = lane; i < DD / 2; i += 32) {
        float2 f = __half22float2(wrow[i]);
        s = fmaf(f.x, o2_b[2 * i], s);
        s = fmaf(f.y, o2_b[2 * i + 1], s);
    }
    #pragma unroll
    for (int off = 16; off > 0; off >>= 1)
        s += __shfl_xor_sync(0xffffffffu, s, off);
    if (lane == 0) buv[gw] = s;
}

// ---------------- fused edge head ---------------------------------------------
// per edge: q = relu(u[src] + v[dst] + w[batch[src]]); pred = sigmoid(q@pc2 + b2)
__global__ __launch_bounds__(256) void edge_head(
    const __half* __restrict__ uv, const __half* __restrict__ w,
    const int* __restrict__ edge_index, const int* __restrict__ batch,
    const float* __restrict__ pc2W /*[768,2]*/, const float* __restrict__ b2,
    const float* __restrict__ lab, float* __restrict__ out, int E)
{
    __shared__ float w0[DD];
    __shared__ float w1[DD];
    for (int i = threadIdx.x; i < DD; i += blockDim.x) {
        w0[i] = pc2W[2 * i];
        w1[i] = pc2W[2 * i + 1];
    }
    __syncthreads();

    int warp = threadIdx.x >> 5;
    int lane = threadIdx.x & 31;
    int e = blockIdx.x * 8 + warp;
    if (e >= E) return;

    int src = edge_index[e];
    int dst = edge_index[E + e];
    int gph = batch[src];

    const __half2* ur = (const __half2*)(uv + (long long)src * (2 * DD));
    const __half2* vr = (const __half2*)(uv + (long long)dst * (2 * DD) + DD);
    const __half2* wr = (const __half2*)(w  + (long long)gph * DD);

    float a0 = 0.f, a1 = 0.f;
    #pragma unroll
    for (int i = 0; i < 12; i++) {
        int k = lane + i * 32;               // half2 index, 0..383
        float2 fu = __half22float2(ur[k]);
        float2 fv = __half22float2(vr[k]);
        float2 fw = __half22float2(wr[k]);
        float q0 = fmaxf(fu.x + fv.x + fw.x, 0.f);
        float q1 = fmaxf(fu.y + fv.y + fw.y, 0.f);
        a0 = fmaf(q0, w0[2*k], a0);   a0 = fmaf(q1, w0[2*k+1], a0);
        a1 = fmaf(q0, w1[2*k], a1);   a1 = fmaf(q1, w1[2*k+1], a1);
    }
    #pragma unroll
    for (int off = 16; off > 0; off >>= 1) {
        a0 += __shfl_xor_sync(0xffffffffu, a0, off);
        a1 += __shfl_xor_sync(0xffffffffu, a1, off);
    }
    if (lane == 0) {
        out[2 * e]     = 1.f / (1.f + expf(-(a0 + b2[0])));
        out[2 * e + 1] = 1.f / (1.f + expf(-(a1 + b2[1])));
        out[2 * E + e] = lab[e];
    }
}

// ---------------- host launch ------------------------------------------------
static __half *p_xh = nullptr, *p_h0 = nullptr, *p_emb3 = nullptr, *p_uv = nullptr,
              *p_yh = nullptr, *p_yp = nullptr, *p_w = nullptr, *p_wT = nullptr;
static float  *p_buv = nullptr, *p_zero = nullptr;

extern "C" void kernel_launch(void* const* d_in, const int* in_sizes, int n_in,
                              void* d_out, int out_size)
{
    if (!p_h0) {  // one-time setup on the (uncaptured) correctness call
        cudaGetSymbolAddress((void**)&p_xh,   g_xh);
        cudaGetSymbolAddress((void**)&p_h0,   g_h0);
        cudaGetSymbolAddress((void**)&p_emb3, g_emb3);
        cudaGetSymbolAddress((void**)&p_uv,   g_uv);
        cudaGetSymbolAddress((void**)&p_yh,   g_yh);
        cudaGetSymbolAddress((void**)&p_yp,   g_yp);
        cudaGetSymbolAddress((void**)&p_w,    g_w);
        cudaGetSymbolAddress((void**)&p_wT,   g_wT);
        cudaGetSymbolAddress((void**)&p_buv,  g_buv);
        cudaGetSymbolAddress((void**)&p_zero, g_zero);
        cudaFuncSetAttribute(mma_gemm, cudaFuncAttributeMaxDynamicSharedMemorySize, DYN_BYTES);
    }

    const float* x          = (const float*)d_in[0];
    const int*   edge_index = (const int*  )d_in[1];
    const int*   batch      = (const int*  )d_in[2];
    const float* y          = (const float*)d_in[5];
    const float* edge_label = (const float*)d_in[6];
    const float* ah_W  = (const float*)d_in[7];
    const float* ah_b  = (const float*)d_in[8];
    const float* c0_W  = (const float*)d_in[9];
    const float* c0_b  = (const float*)d_in[10];
    const float* c1_W  = (const float*)d_in[11];
    const float* c1_b  = (const float*)d_in[12];
    const float* c2_W  = (const float*)d_in[13];
    const float* c2_b  = (const float*)d_in[14];
    const float* o1_W  = (const float*)d_in[15];
    const float* o1_b  = (const float*)d_in[16];
    const float* o2_W  = (const float*)d_in[17];
    const float* o2_b  = (const float*)d_in[18];
    const float* py_W  = (const float*)d_in[19];
    const float* py_b  = (const float*)d_in[20];
    const float* pc1_W = (const float*)d_in[21];
    const float* pc1_b = (const float*)d_in[22];
    const float* pc2_W = (const float*)d_in[23];
    const float* pc2_b = (const float*)d_in[24];

    float* out = (float*)d_out;

    const long long S = (long long)DD * DD;        // 589824
    __half* wt_ah = p_wT;
    __half* wt_c0 = p_wT + S;
    __half* wt_c1 = p_wT + 2 * S;
    __half* wt_c2 = p_wT + 3 * S;
    __half* wt_py = p_wT + 4 * S;
    __half* wt_W1 = p_wT + 5 * S;                  // wt_W1|wt_W2 contiguous (M=1536)
    __half* wt_W3 = p_wT + 7 * S;
    __half* wt_o1 = p_wT + 8 * S;                  // [768, 2304]
    __half* wt_uv = p_wT + 11 * S;                 // composite [1536, 768]
    __half* o2h   = p_wT + 13 * S;                 // o2_W fp16 row-major

    // ---- prep ----
    {
        Ptr8 s8;
        s8.p[0] = ah_W; s8.p[1] = c0_W; s8.p[2] = c1_W; s8.p[3] = c2_W;
        s8.p[4] = py_W;
        s8.p[5] = pc1_W;                 // W1 = rows 0..767
        s8.p[6] = pc1_W + 768 * DD;      // W2
        s8.p[7] = pc1_W + 1536 * DD;     // W3
        transpose8<<<dim3(DD/32, DD/32, 8), 256>>>(s8, p_wT);
        transpose_o1<<<dim3(DD/32, D3/32), 256>>>(o1_W, wt_o1);
        long long tot = ((long long)NN * DD + (long long)GG * DD + (long long)DD * DD) / 4;
        convert_all<<<(unsigned)((tot + 255) / 256), 256>>>(x, y, o2_W, p_xh, p_yh, o2h);
        bias_uv<<<(2 * DD * 32 + 255) / 256, 256>>>(wt_W1, o2_b, p_buv);
        // composite weights, single launch: rows 0..767 from W1, 768..1535 from W2
        dim3 gC(DD / BN, 2 * DD / BM);    // 6 x 12
        mma_gemm<<<gC, 256, DYN_BYTES>>>(wt_W1, DD, o2h, p_zero, wt_uv, DD, 2 * DD, DD, 0);
    }

    dim3 blk(256);
    dim3 gN(DD / BN, (NN + BM - 1) / BM);        // 6 x 313
    dim3 gUV(2 * DD / BN, (NN + BM - 1) / BM);   // 12 x 313
    dim3 gG(DD / BN, 1);

    // Encoder
    mma_gemm<<<gN, blk, DYN_BYTES>>>(p_xh, DD, wt_ah, ah_b, p_h0, DD, NN, DD, 1);
    mma_gemm<<<gN, blk, DYN_BYTES>>>(p_h0, DD, wt_c0, c0_b, p_emb3, D3, NN, DD, 1);
    mma_gemm<<<gN, blk, DYN_BYTES>>>(p_emb3, D3, wt_c1, c1_b, p_emb3 + DD, D3, NN, DD, 1);
    mma_gemm<<<gN, blk, DYN_BYTES>>>(p_emb3 + DD, D3, wt_c2, c2_b, p_emb3 + 2 * DD, D3, NN, DD, 1);
    mma_gemm<<<gN, blk, DYN_BYTES>>>(p_emb3, D3, wt_o1, o1_b, p_h0, DD, NN, D3, 1);
    // uv = t @ [o2W*W1 | o2W*W2] + b_uv   (o2 folded; emb never materialized)
    mma_gemm<<<gUV, blk, DYN_BYTES>>>(p_h0, DD, wt_uv, p_buv, p_uv, 2 * DD, NN, DD, 0);
    // per-graph: yp = leaky(y@py + py_b); w = yp@W3 + pc1_b
    mma_gemm<<<gG, blk, DYN_BYTES>>>(p_yh, DD, wt_py, py_b, p_yp, DD, GG, DD, 2);
    mma_gemm<<<gG, blk, DYN_BYTES>>>(p_yp, DD, wt_W3, pc1_b, p_w, DD, GG, DD, 0);
    // fused edge head: relu(u+v+w) @ pc2 -> sigmoid -> out; std copy
    edge_head<<<(EE + 7) / 8, 256>>>(p_uv, p_w, edge_index, batch,
                                     pc2_W, pc2_b, edge_label, out, EE);

    (void)n_in; (void)in_sizes; (void)out_size;
}